// round 14
// baseline (speedup 1.0000x reference)
#include <cuda_runtime.h>
#include <cstdint>

#define Bn 32
#define Cn 512
#define Nn 1600
#define NCn 20
#define NOUT 25
#define NGRP (Bn * NCn)
#define STRIDEF 32.0f
#define CONF_T 0.3f
#define NMS_T 0.5f
#define CAPK 256
#define CAPB 192

typedef unsigned long long ull;

// ---------------- scratch -----------------------------------------------------
__device__ float g_boxes[Bn * Nn * 4];
__device__ int   g_cnt[NGRP];
__device__ ull   g_keys[NGRP * CAPK];
// B fragments: [ks(64)][nt(4)][lane(32)] -> {bh0, bh1, bl0, bl1} (tf32 bits)
__device__ uint4 g_Bfrag[64 * 4 * 32];

// ---------------- helpers -----------------------------------------------------
__device__ __forceinline__ uint32_t tf32_of(float x) {
    uint32_t r; asm("cvt.rna.tf32.f32 %0, %1;" : "=r"(r) : "f"(x)); return r;
}
__device__ __forceinline__ float sigmoidf_(float x) { return 1.0f / (1.0f + expf(-x)); }

__device__ __forceinline__ void mma_tf32(float* d, uint32_t a0, uint32_t a1,
                                         uint32_t a2, uint32_t a3,
                                         uint32_t b0, uint32_t b1) {
    asm volatile(
        "mma.sync.aligned.m16n8k8.row.col.f32.tf32.tf32.f32 "
        "{%0,%1,%2,%3}, {%4,%5,%6,%7}, {%8,%9}, {%0,%1,%2,%3};"
        : "+f"(d[0]), "+f"(d[1]), "+f"(d[2]), "+f"(d[3])
        : "r"(a0), "r"(a1), "r"(a2), "r"(a3), "r"(b0), "r"(b1));
}

// ---------------- prep: bake B (weights) into tf32 hi/lo fragments -----------
// entry e = (ks*4 + nt)*32 + lane; col(out) = nt*8 + (lane>>2);
// k = ks*8 + (lane&3); b0 at k, b1 at k+4.
__global__ void __launch_bounds__(256) prep_kernel(
    const float* __restrict__ wo, const float* __restrict__ wc,
    const float* __restrict__ wr)
{
    int e = blockIdx.x * 256 + threadIdx.x;      // 0..8191
    int lane = e & 31;
    int nt = (e >> 5) & 3;
    int ks = e >> 7;
    int col = nt * 8 + (lane >> 2);
    int k0 = ks * 8 + (lane & 3);

    float w0 = 0.f, w1 = 0.f;
    if (col == 0)       { w0 = wo[k0];                 w1 = wo[k0 + 4]; }
    else if (col <= 20) { w0 = wc[(col - 1) * Cn + k0]; w1 = wc[(col - 1) * Cn + k0 + 4]; }
    else if (col <= 24) { w0 = wr[(col - 21) * Cn + k0]; w1 = wr[(col - 21) * Cn + k0 + 4]; }

    uint32_t h0 = tf32_of(w0), h1 = tf32_of(w1);
    uint32_t l0 = tf32_of(w0 - __uint_as_float(h0));
    uint32_t l1 = tf32_of(w1 - __uint_as_float(h1));
    g_Bfrag[e] = make_uint4(h0, h1, l0, l1);
}

// ---------------- Kernel A: tf32 mma.sync head, A direct from gmem ----------
// 400 blocks x 256 threads. Warp w: m16 tile = global cells [blk*128+w*16,+16),
// all 512 channels (64 k8-steps), n = 32 outs (25 real). No smem in main loop.
extern __shared__ float smemA[];
#define D_STRIDE 34
#define F_BIAS  (128 * D_STRIDE)       // 4352
#define F_TOTAL (F_BIAS + 32)          // 4384 floats = 17536 B

__global__ void __launch_bounds__(256) head_kernel(
    const float* __restrict__ feat,
    const float* __restrict__ wo, const float* __restrict__ bo,
    const float* __restrict__ wc, const float* __restrict__ bc,
    const float* __restrict__ wr, const float* __restrict__ br,
    float* __restrict__ out)
{
    const int tid  = threadIdx.x;
    const int w    = tid >> 5;
    const int lane = tid & 31;
    const int g    = lane >> 2;          // fragment group row
    const int tg   = lane & 3;           // thread-in-group (k offset)
    float* Dsm  = smemA;
    float* bias = smemA + F_BIAS;

    if (tid < NOUT) {
        float v;
        if (tid == 0)        v = bo[0];
        else if (tid <= NCn) v = bc[tid - 1];
        else                 v = br[tid - 1 - NCn];
        bias[tid] = v;
    }

    // per-lane A row base pointers (rows may straddle batches)
    const int rowA = blockIdx.x * 128 + w * 16 + g;
    const int rowB = rowA + 8;
    const int bA = rowA / Nn, bB = rowB / Nn;
    const float* pA = feat + (size_t)bA * Cn * Nn + (rowA - bA * Nn) + (size_t)tg * Nn;
    const float* pB = feat + (size_t)bB * Cn * Nn + (rowB - bB * Nn) + (size_t)tg * Nn;

    float acc[4][4];
#pragma unroll
    for (int nt = 0; nt < 4; nt++)
#pragma unroll
        for (int r = 0; r < 4; r++) acc[nt][r] = 0.0f;

    const uint4* gB = g_Bfrag;

#pragma unroll 2
    for (int ks = 0; ks < 64; ks++) {
        // A fragment: a0=(g,tg) a1=(g+8,tg) a2=(g,tg+4) a3=(g+8,tg+4)
        float f0 = pA[(size_t)(ks * 8) * Nn];
        float f1 = pB[(size_t)(ks * 8) * Nn];
        float f2 = pA[(size_t)(ks * 8 + 4) * Nn];
        float f3 = pB[(size_t)(ks * 8 + 4) * Nn];
        uint32_t ah0 = tf32_of(f0), ah1 = tf32_of(f1);
        uint32_t ah2 = tf32_of(f2), ah3 = tf32_of(f3);
        uint32_t al0 = tf32_of(f0 - __uint_as_float(ah0));
        uint32_t al1 = tf32_of(f1 - __uint_as_float(ah1));
        uint32_t al2 = tf32_of(f2 - __uint_as_float(ah2));
        uint32_t al3 = tf32_of(f3 - __uint_as_float(ah3));
#pragma unroll
        for (int nt = 0; nt < 4; nt++) {
            uint4 bb = gB[(ks * 4 + nt) * 32 + lane];
            mma_tf32(acc[nt], ah0, ah1, ah2, ah3, bb.x, bb.y);  // Ah*Bh
            mma_tf32(acc[nt], al0, al1, al2, al3, bb.x, bb.y);  // Al*Bh
            mma_tf32(acc[nt], ah0, ah1, ah2, ah3, bb.z, bb.w);  // Ah*Bl
        }
    }

    // exchange D via smem: Dsm[cell_local * 34 + col]
    __syncthreads();   // bias staged; Dsm region free
    {
        int rA = w * 16 + g;       // cell_local of rows g / g+8
#pragma unroll
        for (int nt = 0; nt < 4; nt++) {
            int c = nt * 8 + tg * 2;
            *(float2*)&Dsm[rA * D_STRIDE + c]       = make_float2(acc[nt][0], acc[nt][1]);
            *(float2*)&Dsm[(rA + 8) * D_STRIDE + c] = make_float2(acc[nt][2], acc[nt][3]);
        }
    }
    __syncthreads();

    // epilogue: one cell per thread (threads 0..127)
    if (tid < 128) {
        int cell = blockIdx.x * 128 + tid;
        int eb = cell / Nn;
        int n  = cell - eb * Nn;
        float rr[25];
#pragma unroll
        for (int o = 0; o < NOUT; o++)
            rr[o] = Dsm[tid * D_STRIDE + o] + bias[o];

        float sig_obj = sigmoidf_(rr[0]);
        float best = rr[1]; int lab = 0;
#pragma unroll
        for (int k = 1; k < NCn; k++)
            if (rr[1 + k] > best) { best = rr[1 + k]; lab = k; }
        float score = sqrtf(sig_obj * sigmoidf_(best));

        float gx = (float)(n % 40), gy = (float)(n / 40);
        float cx = (sigmoidf_(rr[21]) + gx) * STRIDEF;
        float cy = (sigmoidf_(rr[22]) + gy) * STRIDEF;
        float bw = expf(rr[23]) * STRIDEF;
        float bh = expf(rr[24]) * STRIDEF;

        int idx = eb * Nn + n;
        float4 bx = make_float4(cx - bw * 0.5f, cy - bh * 0.5f,
                                cx + bw * 0.5f, cy + bh * 0.5f);
        *(float4*)&g_boxes[idx * 4] = bx;
        out[Bn * Nn * 5 + idx] = (float)lab;    // labels region

        int grp = eb * NCn + lab;
        int pos = atomicAdd(&g_cnt[grp], 1);
        unsigned sb = __float_as_uint(score);   // score > 0 always
        if (pos < CAPK)
            g_keys[grp * CAPK + pos] = ((ull)(~sb) << 32) | (unsigned)n;
    }
}

// ---------------- Kernel B: block-per-group NMS (unchanged R12) -------------
__global__ void __launch_bounds__(128) nms_kernel(float* __restrict__ out)
{
    __shared__ ull    k[CAPK];
    __shared__ ull    ks[CAPB];
    __shared__ float4 bx[CAPB];
    __shared__ ull    mk[CAPB * 3];
    __shared__ int    scnt;

    const int tid = threadIdx.x;
    const int grp = blockIdx.x;
    const int b   = grp / NCn;
    const int bIdx = b * Nn;

    int M = g_cnt[grp];
    if (M > CAPB) M = CAPB;
    if (tid == 0) scnt = 0;

    for (int t = tid; t < M; t += 128) k[t] = g_keys[grp * CAPK + t];
    __syncthreads();
    if (tid == 0) g_cnt[grp] = 0;

    // rank sort (keys unique)
    for (int t = tid; t < M; t += 128) {
        ull key = k[t];
        int r = 0;
#pragma unroll 4
        for (int j = 0; j < M; j++)
            r += (k[j] < key) ? 1 : 0;
        ks[r] = key;
    }
    __syncthreads();

    int mc_loc = 0;
    for (int t = tid; t < M; t += 128) {
        int n = (int)(ks[t] & 0xFFFFFFFFULL);
        bx[t] = *(const float4*)&g_boxes[(bIdx + n) * 4];
        float s = __uint_as_float(~(unsigned)(ks[t] >> 32));
        if (s > CONF_T) mc_loc++;
    }
    if (mc_loc) atomicAdd(&scnt, mc_loc);
    __syncthreads();
    const int Mc = scnt;

    for (int t = tid; t < M; t += 128) {
        ull m0 = 0, m1 = 0, m2 = 0;
        float4 A = bx[t];
        float areaA = (A.z - A.x) * (A.w - A.y);
#pragma unroll 4
        for (int j = 0; j < M; j++) {
            float4 Bv = bx[j];
            float x1 = fmaxf(A.x, Bv.x), y1 = fmaxf(A.y, Bv.y);
            float x2 = fminf(A.z, Bv.z), y2 = fminf(A.w, Bv.w);
            float inter = fmaxf(x2 - x1, 0.0f) * fmaxf(y2 - y1, 0.0f);
            float areaB = (Bv.z - Bv.x) * (Bv.w - Bv.y);
            float uni = areaA + areaB - inter;
            bool sup = (j > t) && (inter > NMS_T * uni);
            ull bit = sup ? (1ULL << (j & 63)) : 0ULL;
            if (j < 64)       m0 |= bit;
            else if (j < 128) m1 |= bit;
            else              m2 |= bit;
        }
        mk[t * 3 + 0] = m0; mk[t * 3 + 1] = m1; mk[t * 3 + 2] = m2;
    }
    __syncthreads();

    ull kp0 = (Mc <= 0) ? 0ULL : (Mc >= 64 ? ~0ULL : ((1ULL << Mc) - 1));
    int c1 = Mc - 64;
    ull kp1 = (c1 <= 0) ? 0ULL : (c1 >= 64 ? ~0ULL : ((1ULL << c1) - 1));
    int c2 = Mc - 128;
    ull kp2 = (c2 <= 0) ? 0ULL : (c2 >= 64 ? ~0ULL : ((1ULL << c2) - 1));

#pragma unroll 4
    for (int i = 0; i < Mc; i++) {
        ull m0 = mk[i * 3 + 0], m1 = mk[i * 3 + 1], m2 = mk[i * 3 + 2];
        ull kw = (i < 64) ? kp0 : (i < 128) ? kp1 : kp2;
        if ((kw >> (i & 63)) & 1ULL) {
            kp0 &= ~m0; kp1 &= ~m1; kp2 &= ~m2;
        }
    }

    for (int t = tid; t < M; t += 128) {
        int n = (int)(ks[t] & 0xFFFFFFFFULL);
        int idx = bIdx + n;
        ull kw = (t < 64) ? kp0 : (t < 128) ? kp1 : kp2;
        bool kept = (kw >> (t & 63)) & 1ULL;
        float s = __uint_as_float(~(unsigned)(ks[t] >> 32));
        float4 Bv = bx[t];
        out[idx * 5 + 0] = kept ? Bv.x : 0.0f;
        out[idx * 5 + 1] = kept ? Bv.y : 0.0f;
        out[idx * 5 + 2] = kept ? Bv.z : 0.0f;
        out[idx * 5 + 3] = kept ? Bv.w : 0.0f;
        out[idx * 5 + 4] = kept ? s : 0.0f;
        out[Bn * Nn * 6 + idx] = kept ? 1.0f : 0.0f;
    }
}

// ---------------- launch -----------------------------------------------------
extern "C" void kernel_launch(void* const* d_in, const int* in_sizes, int n_in,
                              void* d_out, int out_size)
{
    const float* feat = (const float*)d_in[0];
    const float* wo   = (const float*)d_in[1];
    const float* bo   = (const float*)d_in[2];
    const float* wc   = (const float*)d_in[3];
    const float* bc   = (const float*)d_in[4];
    const float* wr   = (const float*)d_in[5];
    const float* br   = (const float*)d_in[6];
    float* out = (float*)d_out;

    size_t smem = (size_t)F_TOTAL * sizeof(float);   // 17536 B
    cudaFuncSetAttribute(head_kernel,
                         cudaFuncAttributeMaxDynamicSharedMemorySize, (int)smem);

    prep_kernel<<<32, 256>>>(wo, wc, wr);
    head_kernel<<<400, 256, smem>>>(feat, wo, bo, wc, bc, wr, br, out);
    nms_kernel<<<NGRP, 128>>>(out);
}